// round 6
// baseline (speedup 1.0000x reference)
#include <cuda_runtime.h>
#include <cuda_bf16.h>

// IrradiationSingleTimestep — round 6: register-rolling nested stencil.
// Block = 8 warps x 32 lanes x 4 floats = full 1024-wide row; marches 16 rows.
// Field warp-edge neighbors come from (prefetched) global scalar loads ->
// only ONE __syncthreads per iteration (dF edge exchange, double-buffered).

#define W     1024
#define BAT   8
#define RPB   16             // output rows per block
#define NW    8              // warps per block
#define EPSV  1e-6f
#define DTV   1e-2f

__device__ __forceinline__ float4 lap4(float4 c, float L, float R, float4 u, float4 d) {
    float4 r;
    r.x = L   + c.y + u.x + d.x - 4.0f * c.x;
    r.y = c.x + c.z + u.y + d.y - 4.0f * c.y;
    r.z = c.y + c.w + u.z + d.z - 4.0f * c.z;
    r.w = c.z + R   + u.w + d.w - 4.0f * c.w;
    return r;
}
__device__ __forceinline__ float lane_of(const float4& v, int k) {
    return k == 0 ? v.x : (k == 1 ? v.y : (k == 2 ? v.z : v.w));
}
__device__ __forceinline__ void set_lane(float4& v, int k, float x) {
    if (k == 0) v.x = x; else if (k == 1) v.y = x; else if (k == 2) v.z = x; else v.w = x;
}

__global__ __launch_bounds__(NW * 32, 2)
void irr_roll_kernel(const float* __restrict__ cv_g,
                     const float* __restrict__ ci_g,
                     const float* __restrict__ eta_g,
                     const float* __restrict__ p_ev,
                     const float* __restrict__ p_ei,
                     const float* __restrict__ p_kbt,
                     const float* __restrict__ p_kv,
                     const float* __restrict__ p_ki,
                     const float* __restrict__ p_ke,
                     const float* __restrict__ p_dv,
                     const float* __restrict__ p_di,
                     const float* __restrict__ p_L,
                     float* __restrict__ out)
{
    // dF edge exchange, double-buffered by iteration parity.
    // [parity][warp][0]=dfv, [1]=dfi
    __shared__ float sLb[2][NW][2];   // lane0 .x
    __shared__ float sRb[2][NW][2];   // lane31 .w

    const int lane = threadIdx.x & 31;
    const int wl   = threadIdx.x >> 5;
    const int x    = (wl << 7) + (lane << 2);       // 0..1020, step 4
    const int y0   = blockIdx.y * RPB;
    const int b    = blockIdx.z;

    const size_t plane = (size_t)W * W;
    const size_t fld   = (size_t)BAT * plane;
    const size_t basec = (size_t)b * plane + x;
    const size_t baseb = (size_t)b * plane;

    const float energy_v  = fabsf(*p_ev)  + 0.001f;
    const float energy_i  = fabsf(*p_ei)  + 0.001f;
    const float kBT       = fabsf(*p_kbt) + 0.001f;
    const float kappa_v   = fabsf(*p_kv)  + 0.001f;
    const float kappa_i   = fabsf(*p_ki)  + 0.001f;
    const float kappa_eta = fabsf(*p_ke)  + 0.001f;
    const float diff_v    = fabsf(*p_dv)  + 0.001f;
    const float diff_i    = fabsf(*p_di)  + 0.001f;
    const float Lp        = fabsf(*p_L)   + 0.001f;
    const float inv_kBT   = 1.0f / kBT;

#define LDROW(p, row) (*(const float4*)((p) + basec + ((size_t)((row) & (W - 1)) << 10)))

    // Per-warp field edge column (left for lane 0, right for lane 31).
    const bool edge  = (lane == 0) | (lane == 31);
    const int  ecol  = (lane == 0) ? ((x - 1) & (W - 1)) : ((x + 4) & (W - 1));
#define LDEDGE(p, row) ((p)[baseb + ((size_t)((row) & (W - 1)) << 10) + ecol])

    // Rolling field rows: m1 = row ri-1, c0 = row ri, p1 = row ri+1
    float4 cvm1 = LDROW(cv_g,  y0 - 2), cv0 = LDROW(cv_g,  y0 - 1), cvp1;
    float4 cim1 = LDROW(ci_g,  y0 - 2), ci0 = LDROW(ci_g,  y0 - 1), cip1;
    float4 etm1 = LDROW(eta_g, y0 - 2), et0 = LDROW(eta_g, y0 - 1), etp1;

    // Field edge scalars for the current row ri (valid on lanes 0/31 only).
    float eCv = 0.f, eCi = 0.f, eEt = 0.f;
    if (edge) {
        eCv = LDEDGE(cv_g,  y0 - 1);
        eCi = LDEDGE(ci_g,  y0 - 1);
        eEt = LDEDGE(eta_g, y0 - 1);
    }

    // Rolling dF rows: A = ri-2, B = ri-1 (C = ri computed in-loop)
    float4 dvA, dvB, diA, diB;
    float eBvL = 0.f, eBvR = 0.f, eBiL = 0.f, eBiR = 0.f;

    const int wlm1 = (wl + NW - 1) & (NW - 1);
    const int wlp1 = (wl + 1) & (NW - 1);

    for (int i = 0; i < RPB + 2; i++) {
        const int ri = y0 - 1 + i;
        const int p  = i & 1;

        // Prefetch field row ri+1 (vector) + its edge scalars.
        cvp1 = LDROW(cv_g,  ri + 1);
        cip1 = LDROW(ci_g,  ri + 1);
        etp1 = LDROW(eta_g, ri + 1);
        float nCv = 0.f, nCi = 0.f, nEt = 0.f;
        if (edge) {
            nCv = LDEDGE(cv_g,  ri + 1);
            nCi = LDEDGE(ci_g,  ri + 1);
            nEt = LDEDGE(eta_g, ri + 1);
        }

        // ---- field x-neighbors of row ri: shuffles + global edges ----
        float cvL = __shfl_up_sync(0xffffffffu, cv0.w, 1);
        float ciL = __shfl_up_sync(0xffffffffu, ci0.w, 1);
        float etL = __shfl_up_sync(0xffffffffu, et0.w, 1);
        float cvR = __shfl_down_sync(0xffffffffu, cv0.x, 1);
        float ciR = __shfl_down_sync(0xffffffffu, ci0.x, 1);
        float etR = __shfl_down_sync(0xffffffffu, et0.x, 1);
        if (lane == 0)  { cvL = eCv; ciL = eCi; etL = eEt; }
        if (lane == 31) { cvR = eCv; ciR = eCi; etR = eEt; }

        // ---- dF row ri + eta_new ----
        const float4 lcv4 = lap4(cv0, cvL, cvR, cvm1, cvp1);
        const float4 lci4 = lap4(ci0, ciL, ciR, cim1, cip1);
        const float4 let4 = lap4(et0, etL, etR, etm1, etp1);

        float4 dvC, diC, en4;
        #pragma unroll
        for (int k = 0; k < 4; k++) {
            const float cv  = lane_of(cv0, k);
            const float ci  = lane_of(ci0, k);
            const float eta = lane_of(et0, k);

            const float cs  = 1.0f - cv - ci;
            const float lcv = __logf(fmaxf(cv, EPSV));
            const float lci = __logf(fmaxf(ci, EPSV));
            const float lcs = __logf(fmaxf(cs, EPSV));

            const float em1 = eta - 1.0f;
            const float h   = em1 * em1;
            const float jj  = eta * eta;

            const float dfs_dcv = energy_v + kBT * (lcv - lcs);
            const float dfs_dci = energy_i + kBT * (lci - lcs);

            set_lane(dvC, k, h * dfs_dcv + jj * (2.0f * (cv - 1.0f)) - kappa_v * lane_of(lcv4, k));
            set_lane(diC, k, h * dfs_dci + jj * (2.0f * ci)          - kappa_i * lane_of(lci4, k));

            const float fs = energy_v * cv + energy_i * ci
                           + kBT * (cv * lcv + ci * lci + cs * lcs);
            const float cq = cv - 1.0f;
            const float fv = cq * cq + ci * ci;
            const float dFe = fs * (2.0f * em1) + fv * (2.0f * eta)
                            - kappa_eta * lane_of(let4, k);
            set_lane(en4, k, fminf(fmaxf(eta - DTV * (Lp * dFe), 0.0f), 1.0f));
        }

        if (i >= 1 && i <= RPB) {
            *(float4*)&out[2 * fld + basec + ((size_t)ri << 10)] = en4;
        }

        // ---- dF x-edge exchange (single barrier, parity double buffer) ----
        if (lane == 0)  { sLb[p][wl][0] = dvC.x; sLb[p][wl][1] = diC.x; }
        if (lane == 31) { sRb[p][wl][0] = dvC.w; sRb[p][wl][1] = diC.w; }
        __syncthreads();

        float eCvL = __shfl_up_sync(0xffffffffu, dvC.w, 1);
        float eCiL = __shfl_up_sync(0xffffffffu, diC.w, 1);
        float eCvR = __shfl_down_sync(0xffffffffu, dvC.x, 1);
        float eCiR = __shfl_down_sync(0xffffffffu, diC.x, 1);
        if (lane == 0)  { eCvL = sRb[p][wlm1][0]; eCiL = sRb[p][wlm1][1]; }
        if (lane == 31) { eCvR = sLb[p][wlp1][0]; eCiR = sLb[p][wlp1][1]; }

        // ---- output row ro = ri-1 ----
        if (i >= 2) {
            const int ro = ri - 1;
            const float4 ldv = lap4(dvB, eBvL, eBvR, dvA, dvC);
            const float4 ldi = lap4(diB, eBiL, eBiR, diA, diC);

            float4 cvn, cin;
            #pragma unroll
            for (int k = 0; k < 4; k++) {
                const float cv = lane_of(cvm1, k);   // field row ri-1 = ro
                const float ci = lane_of(cim1, k);
                const float mv = diff_v * cv * inv_kBT;
                const float mi = diff_i * ci * inv_kBT;
                set_lane(cvn, k, fminf(fmaxf(cv + DTV * (mv * lane_of(ldv, k)), 0.0f), 1.0f));
                set_lane(cin, k, fminf(fmaxf(ci + DTV * (mi * lane_of(ldi, k)), 0.0f), 1.0f));
            }
            const size_t o = basec + ((size_t)ro << 10);
            *(float4*)&out[o]       = cvn;
            *(float4*)&out[fld + o] = cin;
        }

        // ---- rotate ----
        dvA = dvB; dvB = dvC; diA = diB; diB = diC;
        eBvL = eCvL; eBvR = eCvR; eBiL = eCiL; eBiR = eCiR;
        cvm1 = cv0; cv0 = cvp1;
        cim1 = ci0; ci0 = cip1;
        etm1 = et0; et0 = etp1;
        eCv = nCv; eCi = nCi; eEt = nEt;
    }
#undef LDROW
#undef LDEDGE
}

extern "C" void kernel_launch(void* const* d_in, const int* in_sizes, int n_in,
                              void* d_out, int out_size)
{
    const float* cv  = (const float*)d_in[0];
    const float* ci  = (const float*)d_in[1];
    const float* eta = (const float*)d_in[2];
    const float* ev  = (const float*)d_in[3];
    const float* ei  = (const float*)d_in[4];
    const float* kbt = (const float*)d_in[5];
    const float* kv  = (const float*)d_in[6];
    const float* ki  = (const float*)d_in[7];
    const float* ke  = (const float*)d_in[8];
    const float* dv  = (const float*)d_in[9];
    const float* di  = (const float*)d_in[10];
    const float* L   = (const float*)d_in[11];
    float* out = (float*)d_out;

    dim3 block(NW * 32, 1, 1);
    dim3 grid(1, W / RPB, BAT);
    irr_roll_kernel<<<grid, block>>>(cv, ci, eta, ev, ei, kbt, kv, ki, ke,
                                     dv, di, L, out);
}

// round 9
// speedup vs baseline: 1.0587x; 1.0587x over previous
#include <cuda_runtime.h>
#include <cuda_bf16.h>

// IrradiationSingleTimestep — round 7: barrier-free independent-warp rolling
// stencil. Each warp owns a 128-wide strip (32 lanes x float4) and marches 8
// rows. NO shared memory, NO __syncthreads: the dF halo column just outside
// the strip is redundantly computed by lanes 0/31 from a few scalar global
// loads. All other x-neighbors via warp shuffles.

#define W     1024
#define BAT   8
#define RPB   8
#define EPSV  1e-6f
#define DTV   1e-2f

__device__ __forceinline__ float4 lap4(float4 c, float L, float R, float4 u, float4 d) {
    float4 r;
    r.x = L   + c.y + u.x + d.x - 4.0f * c.x;
    r.y = c.x + c.z + u.y + d.y - 4.0f * c.y;
    r.z = c.y + c.w + u.z + d.z - 4.0f * c.z;
    r.w = c.z + R   + u.w + d.w - 4.0f * c.w;
    return r;
}
__device__ __forceinline__ float lane_of(const float4& v, int k) {
    return k == 0 ? v.x : (k == 1 ? v.y : (k == 2 ? v.z : v.w));
}
__device__ __forceinline__ void set_lane(float4& v, int k, float x) {
    if (k == 0) v.x = x; else if (k == 1) v.y = x; else if (k == 2) v.z = x; else v.w = x;
}

__global__ __launch_bounds__(128, 4)
void irr_warp_kernel(const float* __restrict__ cv_g,
                     const float* __restrict__ ci_g,
                     const float* __restrict__ eta_g,
                     const float* __restrict__ p_ev,
                     const float* __restrict__ p_ei,
                     const float* __restrict__ p_kbt,
                     const float* __restrict__ p_kv,
                     const float* __restrict__ p_ki,
                     const float* __restrict__ p_ke,
                     const float* __restrict__ p_dv,
                     const float* __restrict__ p_di,
                     const float* __restrict__ p_L,
                     float* __restrict__ out)
{
    const int lane  = threadIdx.x & 31;
    const int wl    = threadIdx.x >> 5;
    const int strip = blockIdx.x * 4 + wl;          // 0..7
    const int x     = (strip << 7) + (lane << 2);   // lane's 4 columns
    const int y0    = blockIdx.y * RPB;
    const int b     = blockIdx.z;

    const size_t plane = (size_t)W * W;
    const size_t fld   = (size_t)BAT * plane;
    const size_t baseb = (size_t)b * plane;
    const size_t basec = baseb + x;

    const float energy_v  = fabsf(*p_ev)  + 0.001f;
    const float energy_i  = fabsf(*p_ei)  + 0.001f;
    const float kBT       = fabsf(*p_kbt) + 0.001f;
    const float kappa_v   = fabsf(*p_kv)  + 0.001f;
    const float kappa_i   = fabsf(*p_ki)  + 0.001f;
    const float kappa_eta = fabsf(*p_ke)  + 0.001f;
    const float diff_v    = fabsf(*p_dv)  + 0.001f;
    const float diff_i    = fabsf(*p_di)  + 0.001f;
    const float Lp        = fabsf(*p_L)   + 0.001f;
    const float inv_kBT   = 1.0f / kBT;

#define LDROW(p, row) (*(const float4*)((p) + basec + ((size_t)((row) & (W - 1)) << 10)))

    // Halo columns just outside the warp's strip (lane 0: left, lane 31: right)
    const bool edge = (lane == 0) | (lane == 31);
    const int  eo1  = (lane == 0) ? ((x - 1) & (W - 1)) : ((x + 4) & (W - 1));
    const int  eo2  = (lane == 0) ? ((x - 2) & (W - 1)) : ((x + 5) & (W - 1));
#define LDE(p, col, row) ((p)[baseb + ((size_t)((row) & (W - 1)) << 10) + (col)])

    // Rolling field rows
    float4 cvm1 = LDROW(cv_g,  y0 - 2), cv0 = LDROW(cv_g,  y0 - 1), cvp1;
    float4 cim1 = LDROW(ci_g,  y0 - 2), ci0 = LDROW(ci_g,  y0 - 1), cip1;
    float4 etm1 = LDROW(eta_g, y0 - 2), et0 = LDROW(eta_g, y0 - 1), etp1;

    // Halo rolling scalars (edge lanes only; junk elsewhere)
    float hcv_a = 0.f, hcv_b = 0.f, hci_a = 0.f, hci_b = 0.f, het_b = 0.f;
    float gcv_b = 0.f, gci_b = 0.f;     // outer column eo2 at row ri
    if (edge) {
        hcv_a = LDE(cv_g,  eo1, y0 - 2);  hcv_b = LDE(cv_g,  eo1, y0 - 1);
        hci_a = LDE(ci_g,  eo1, y0 - 2);  hci_b = LDE(ci_g,  eo1, y0 - 1);
        het_b = LDE(eta_g, eo1, y0 - 1);
        gcv_b = LDE(cv_g,  eo2, y0 - 1);
        gci_b = LDE(ci_g,  eo2, y0 - 1);
    }

    // Rolling dF rows + halo dF of previous row
    float4 dvA, dvB, diA, diB;
    float hpdv = 0.f, hpdi = 0.f;

    for (int i = 0; i < RPB + 2; i++) {
        const int ri = y0 - 1 + i;

        // ---- prefetch row ri+1 (vector + halo scalars) ----
        cvp1 = LDROW(cv_g,  ri + 1);
        cip1 = LDROW(ci_g,  ri + 1);
        etp1 = LDROW(eta_g, ri + 1);
        float hcv_c = 0.f, hci_c = 0.f, het_c = 0.f, gcv_c = 0.f, gci_c = 0.f;
        if (edge) {
            hcv_c = LDE(cv_g,  eo1, ri + 1);
            hci_c = LDE(ci_g,  eo1, ri + 1);
            het_c = LDE(eta_g, eo1, ri + 1);
            gcv_c = LDE(cv_g,  eo2, ri + 1);
            gci_c = LDE(ci_g,  eo2, ri + 1);
        }

        // ---- field x-neighbors of row ri (shuffles; halo from rolling regs) ----
        float cvL = __shfl_up_sync(0xffffffffu, cv0.w, 1);
        float ciL = __shfl_up_sync(0xffffffffu, ci0.w, 1);
        float etL = __shfl_up_sync(0xffffffffu, et0.w, 1);
        float cvR = __shfl_down_sync(0xffffffffu, cv0.x, 1);
        float ciR = __shfl_down_sync(0xffffffffu, ci0.x, 1);
        float etR = __shfl_down_sync(0xffffffffu, et0.x, 1);
        if (lane == 0)  { cvL = hcv_b; ciL = hci_b; etL = het_b; }
        if (lane == 31) { cvR = hcv_b; ciR = hci_b; etR = het_b; }

        // ---- dF row ri (vector) + eta_new ----
        const float4 lcv4 = lap4(cv0, cvL, cvR, cvm1, cvp1);
        const float4 lci4 = lap4(ci0, ciL, ciR, cim1, cip1);
        const float4 let4 = lap4(et0, etL, etR, etm1, etp1);

        float4 dvC, diC, en4;
        #pragma unroll
        for (int k = 0; k < 4; k++) {
            const float cv  = lane_of(cv0, k);
            const float ci  = lane_of(ci0, k);
            const float eta = lane_of(et0, k);

            const float cs  = 1.0f - cv - ci;
            const float lcv = __logf(fmaxf(cv, EPSV));
            const float lci = __logf(fmaxf(ci, EPSV));
            const float lcs = __logf(fmaxf(cs, EPSV));

            const float em1 = eta - 1.0f;
            const float h   = em1 * em1;
            const float jj  = eta * eta;

            const float dfs_dcv = energy_v + kBT * (lcv - lcs);
            const float dfs_dci = energy_i + kBT * (lci - lcs);

            set_lane(dvC, k, h * dfs_dcv + jj * (2.0f * (cv - 1.0f)) - kappa_v * lane_of(lcv4, k));
            set_lane(diC, k, h * dfs_dci + jj * (2.0f * ci)          - kappa_i * lane_of(lci4, k));

            const float fs = energy_v * cv + energy_i * ci
                           + kBT * (cv * lcv + ci * lci + cs * lcs);
            const float cq = cv - 1.0f;
            const float fv = cq * cq + ci * ci;
            const float dFe = fs * (2.0f * em1) + fv * (2.0f * eta)
                            - kappa_eta * lane_of(let4, k);
            set_lane(en4, k, fminf(fmaxf(eta - DTV * (Lp * dFe), 0.0f), 1.0f));
        }

        if (i >= 1 && i <= RPB) {
            *(float4*)&out[2 * fld + basec + ((size_t)ri << 10)] = en4;
        }

        // ---- halo dF at (eo1, ri): redundant scalar compute on edge lanes ----
        float hdv = 0.f, hdi = 0.f;
        if (edge) {
            const float inner_cv = (lane == 0) ? cv0.x : cv0.w;
            const float inner_ci = (lane == 0) ? ci0.x : ci0.w;
            const float lap_hcv = gcv_b + inner_cv + hcv_a + hcv_c - 4.0f * hcv_b;
            const float lap_hci = gci_b + inner_ci + hci_a + hci_c - 4.0f * hci_b;

            const float cs  = 1.0f - hcv_b - hci_b;
            const float lcv = __logf(fmaxf(hcv_b, EPSV));
            const float lci = __logf(fmaxf(hci_b, EPSV));
            const float lcs = __logf(fmaxf(cs, EPSV));
            const float em1 = het_b - 1.0f;
            const float h   = em1 * em1;
            const float jj  = het_b * het_b;

            hdv = h * (energy_v + kBT * (lcv - lcs)) + jj * (2.0f * (hcv_b - 1.0f)) - kappa_v * lap_hcv;
            hdi = h * (energy_i + kBT * (lci - lcs)) + jj * (2.0f * hci_b)          - kappa_i * lap_hci;
        }

        // ---- output row ro = ri-1 (outer Laplacian of dF) ----
        if (i >= 2) {
            const int ro = ri - 1;
            float eLv = __shfl_up_sync(0xffffffffu, dvB.w, 1);
            float eLi = __shfl_up_sync(0xffffffffu, diB.w, 1);
            float eRv = __shfl_down_sync(0xffffffffu, dvB.x, 1);
            float eRi = __shfl_down_sync(0xffffffffu, diB.x, 1);
            if (lane == 0)  { eLv = hpdv; eLi = hpdi; }
            if (lane == 31) { eRv = hpdv; eRi = hpdi; }

            const float4 ldv = lap4(dvB, eLv, eRv, dvA, dvC);
            const float4 ldi = lap4(diB, eLi, eRi, diA, diC);

            float4 cvn, cin;
            #pragma unroll
            for (int k = 0; k < 4; k++) {
                const float cv = lane_of(cvm1, k);   // field row ri-1 = ro
                const float ci = lane_of(cim1, k);
                const float mv = diff_v * cv * inv_kBT;
                const float mi = diff_i * ci * inv_kBT;
                set_lane(cvn, k, fminf(fmaxf(cv + DTV * (mv * lane_of(ldv, k)), 0.0f), 1.0f));
                set_lane(cin, k, fminf(fmaxf(ci + DTV * (mi * lane_of(ldi, k)), 0.0f), 1.0f));
            }
            const size_t o = basec + ((size_t)ro << 10);
            *(float4*)&out[o]       = cvn;
            *(float4*)&out[fld + o] = cin;
        }

        // ---- rotate ----
        dvA = dvB; dvB = dvC; diA = diB; diB = diC;
        hpdv = hdv; hpdi = hdi;
        cvm1 = cv0; cv0 = cvp1;
        cim1 = ci0; ci0 = cip1;
        etm1 = et0; et0 = etp1;
        hcv_a = hcv_b; hcv_b = hcv_c;
        hci_a = hci_b; hci_b = hci_c;
        het_b = het_c;
        gcv_b = gcv_c; gci_b = gci_c;
    }
#undef LDROW
#undef LDE
}

extern "C" void kernel_launch(void* const* d_in, const int* in_sizes, int n_in,
                              void* d_out, int out_size)
{
    const float* cv  = (const float*)d_in[0];
    const float* ci  = (const float*)d_in[1];
    const float* eta = (const float*)d_in[2];
    const float* ev  = (const float*)d_in[3];
    const float* ei  = (const float*)d_in[4];
    const float* kbt = (const float*)d_in[5];
    const float* kv  = (const float*)d_in[6];
    const float* ki  = (const float*)d_in[7];
    const float* ke  = (const float*)d_in[8];
    const float* dv  = (const float*)d_in[9];
    const float* di  = (const float*)d_in[10];
    const float* L   = (const float*)d_in[11];
    float* out = (float*)d_out;

    dim3 block(128, 1, 1);
    dim3 grid(2, W / RPB, BAT);   // 2 blocks x 4 warps = 8 strips of 128 cols
    irr_warp_kernel<<<grid, block>>>(cv, ci, eta, ev, ei, kbt, kv, ki, ke,
                                     dv, di, L, out);
}

// round 11
// speedup vs baseline: 1.2340x; 1.1656x over previous
#include <cuda_runtime.h>
#include <cuda_bf16.h>

// IrradiationSingleTimestep — round 10: barrier-free independent-warp rolling
// stencil with DEEP software pipelining. Each warp owns a 128-wide strip and
// marches 16 rows. Vector row loads are issued one full iteration before
// first use (4-row rolling buffer), hiding LDG latency at low occupancy.
// No shared memory, no __syncthreads; dF halo columns redundantly computed
// by lanes 0/31.

#define W     1024
#define BAT   8
#define RPB   16
#define EPSV  1e-6f
#define DTV   1e-2f

__device__ __forceinline__ float4 lap4(float4 c, float L, float R, float4 u, float4 d) {
    float4 r;
    r.x = L   + c.y + u.x + d.x - 4.0f * c.x;
    r.y = c.x + c.z + u.y + d.y - 4.0f * c.y;
    r.z = c.y + c.w + u.z + d.z - 4.0f * c.z;
    r.w = c.z + R   + u.w + d.w - 4.0f * c.w;
    return r;
}
__device__ __forceinline__ float lane_of(const float4& v, int k) {
    return k == 0 ? v.x : (k == 1 ? v.y : (k == 2 ? v.z : v.w));
}
__device__ __forceinline__ void set_lane(float4& v, int k, float x) {
    if (k == 0) v.x = x; else if (k == 1) v.y = x; else if (k == 2) v.z = x; else v.w = x;
}

__global__ __launch_bounds__(128, 4)
void irr_warp_kernel(const float* __restrict__ cv_g,
                     const float* __restrict__ ci_g,
                     const float* __restrict__ eta_g,
                     const float* __restrict__ p_ev,
                     const float* __restrict__ p_ei,
                     const float* __restrict__ p_kbt,
                     const float* __restrict__ p_kv,
                     const float* __restrict__ p_ki,
                     const float* __restrict__ p_ke,
                     const float* __restrict__ p_dv,
                     const float* __restrict__ p_di,
                     const float* __restrict__ p_L,
                     float* __restrict__ out)
{
    const int lane  = threadIdx.x & 31;
    const int wl    = threadIdx.x >> 5;
    const int strip = blockIdx.x * 4 + wl;          // 0..7
    const int x     = (strip << 7) + (lane << 2);
    const int y0    = blockIdx.y * RPB;
    const int b     = blockIdx.z;

    const size_t plane = (size_t)W * W;
    const size_t fld   = (size_t)BAT * plane;
    const size_t baseb = (size_t)b * plane;
    const size_t basec = baseb + x;

    const float energy_v  = fabsf(*p_ev)  + 0.001f;
    const float energy_i  = fabsf(*p_ei)  + 0.001f;
    const float kBT       = fabsf(*p_kbt) + 0.001f;
    const float kappa_v   = fabsf(*p_kv)  + 0.001f;
    const float kappa_i   = fabsf(*p_ki)  + 0.001f;
    const float kappa_eta = fabsf(*p_ke)  + 0.001f;
    const float diff_v    = fabsf(*p_dv)  + 0.001f;
    const float diff_i    = fabsf(*p_di)  + 0.001f;
    const float Lp        = fabsf(*p_L)   + 0.001f;
    const float inv_kBT   = 1.0f / kBT;

#define LDROW(p, row) (*(const float4*)((p) + basec + ((size_t)((row) & (W - 1)) << 10)))

    const bool edge = (lane == 0) | (lane == 31);
    const int  eo1  = (lane == 0) ? ((x - 1) & (W - 1)) : ((x + 4) & (W - 1));
    const int  eo2  = (lane == 0) ? ((x - 2) & (W - 1)) : ((x + 5) & (W - 1));
#define LDE(p, col, row) ((p)[baseb + ((size_t)((row) & (W - 1)) << 10) + (col)])

    // Rolling field rows: m1 = ri-1, c0 = ri, p1 = ri+1 (pre-loaded), p2 = incoming
    float4 cvm1 = LDROW(cv_g,  y0 - 2), cv0 = LDROW(cv_g,  y0 - 1), cvp1 = LDROW(cv_g,  y0);
    float4 cim1 = LDROW(ci_g,  y0 - 2), ci0 = LDROW(ci_g,  y0 - 1), cip1 = LDROW(ci_g,  y0);
    float4 etm1 = LDROW(eta_g, y0 - 2), et0 = LDROW(eta_g, y0 - 1), etp1 = LDROW(eta_g, y0);

    // Halo rolling scalars (edge lanes only)
    float hcv_a = 0.f, hcv_b = 0.f, hci_a = 0.f, hci_b = 0.f, het_b = 0.f;
    float gcv_b = 0.f, gci_b = 0.f;
    if (edge) {
        hcv_a = LDE(cv_g,  eo1, y0 - 2);  hcv_b = LDE(cv_g,  eo1, y0 - 1);
        hci_a = LDE(ci_g,  eo1, y0 - 2);  hci_b = LDE(ci_g,  eo1, y0 - 1);
        het_b = LDE(eta_g, eo1, y0 - 1);
        gcv_b = LDE(cv_g,  eo2, y0 - 1);
        gci_b = LDE(ci_g,  eo2, y0 - 1);
    }

    float4 dvA, dvB, diA, diB;
    float hpdv = 0.f, hpdi = 0.f;

    for (int i = 0; i < RPB + 2; i++) {
        const int ri = y0 - 1 + i;

        // ---- issue loads row ri+2 (consumed NEXT iteration) ----
        float4 cvp2, cip2, etp2;
        if (i <= RPB) {
            cvp2 = LDROW(cv_g,  ri + 2);
            cip2 = LDROW(ci_g,  ri + 2);
            etp2 = LDROW(eta_g, ri + 2);
        }
        // halo scalars for row ri+1 (used this iteration's halo-dF as _c,
        // and become _b next iteration)
        float hcv_c = 0.f, hci_c = 0.f, het_c = 0.f, gcv_c = 0.f, gci_c = 0.f;
        if (edge) {
            hcv_c = LDE(cv_g,  eo1, ri + 1);
            hci_c = LDE(ci_g,  eo1, ri + 1);
            het_c = LDE(eta_g, eo1, ri + 1);
            gcv_c = LDE(cv_g,  eo2, ri + 1);
            gci_c = LDE(ci_g,  eo2, ri + 1);
        }

        // ---- field x-neighbors of row ri ----
        float cvL = __shfl_up_sync(0xffffffffu, cv0.w, 1);
        float ciL = __shfl_up_sync(0xffffffffu, ci0.w, 1);
        float etL = __shfl_up_sync(0xffffffffu, et0.w, 1);
        float cvR = __shfl_down_sync(0xffffffffu, cv0.x, 1);
        float ciR = __shfl_down_sync(0xffffffffu, ci0.x, 1);
        float etR = __shfl_down_sync(0xffffffffu, et0.x, 1);
        if (lane == 0)  { cvL = hcv_b; ciL = hci_b; etL = het_b; }
        if (lane == 31) { cvR = hcv_b; ciR = hci_b; etR = het_b; }

        // ---- dF row ri + eta_new (p1 was loaded LAST iteration: latency hidden) ----
        const float4 lcv4 = lap4(cv0, cvL, cvR, cvm1, cvp1);
        const float4 lci4 = lap4(ci0, ciL, ciR, cim1, cip1);
        const float4 let4 = lap4(et0, etL, etR, etm1, etp1);

        float4 dvC, diC, en4;
        #pragma unroll
        for (int k = 0; k < 4; k++) {
            const float cv  = lane_of(cv0, k);
            const float ci  = lane_of(ci0, k);
            const float eta = lane_of(et0, k);

            const float cs  = 1.0f - cv - ci;
            const float lcv = __logf(fmaxf(cv, EPSV));
            const float lci = __logf(fmaxf(ci, EPSV));
            const float lcs = __logf(fmaxf(cs, EPSV));

            const float em1 = eta - 1.0f;
            const float h   = em1 * em1;
            const float jj  = eta * eta;

            const float dfs_dcv = energy_v + kBT * (lcv - lcs);
            const float dfs_dci = energy_i + kBT * (lci - lcs);

            set_lane(dvC, k, h * dfs_dcv + jj * (2.0f * (cv - 1.0f)) - kappa_v * lane_of(lcv4, k));
            set_lane(diC, k, h * dfs_dci + jj * (2.0f * ci)          - kappa_i * lane_of(lci4, k));

            const float fs = energy_v * cv + energy_i * ci
                           + kBT * (cv * lcv + ci * lci + cs * lcs);
            const float cq = cv - 1.0f;
            const float fv = cq * cq + ci * ci;
            const float dFe = fs * (2.0f * em1) + fv * (2.0f * eta)
                            - kappa_eta * lane_of(let4, k);
            set_lane(en4, k, fminf(fmaxf(eta - DTV * (Lp * dFe), 0.0f), 1.0f));
        }

        if (i >= 1 && i <= RPB) {
            *(float4*)&out[2 * fld + basec + ((size_t)ri << 10)] = en4;
        }

        // ---- halo dF at (eo1, ri) on edge lanes ----
        float hdv = 0.f, hdi = 0.f;
        if (edge) {
            const float inner_cv = (lane == 0) ? cv0.x : cv0.w;
            const float inner_ci = (lane == 0) ? ci0.x : ci0.w;
            const float lap_hcv = gcv_b + inner_cv + hcv_a + hcv_c - 4.0f * hcv_b;
            const float lap_hci = gci_b + inner_ci + hci_a + hci_c - 4.0f * hci_b;

            const float cs  = 1.0f - hcv_b - hci_b;
            const float lcv = __logf(fmaxf(hcv_b, EPSV));
            const float lci = __logf(fmaxf(hci_b, EPSV));
            const float lcs = __logf(fmaxf(cs, EPSV));
            const float em1 = het_b - 1.0f;
            const float h   = em1 * em1;
            const float jj  = het_b * het_b;

            hdv = h * (energy_v + kBT * (lcv - lcs)) + jj * (2.0f * (hcv_b - 1.0f)) - kappa_v * lap_hcv;
            hdi = h * (energy_i + kBT * (lci - lcs)) + jj * (2.0f * hci_b)          - kappa_i * lap_hci;
        }

        // ---- output row ro = ri-1 ----
        if (i >= 2) {
            const int ro = ri - 1;
            float eLv = __shfl_up_sync(0xffffffffu, dvB.w, 1);
            float eLi = __shfl_up_sync(0xffffffffu, diB.w, 1);
            float eRv = __shfl_down_sync(0xffffffffu, dvB.x, 1);
            float eRi = __shfl_down_sync(0xffffffffu, diB.x, 1);
            if (lane == 0)  { eLv = hpdv; eLi = hpdi; }
            if (lane == 31) { eRv = hpdv; eRi = hpdi; }

            const float4 ldv = lap4(dvB, eLv, eRv, dvA, dvC);
            const float4 ldi = lap4(diB, eLi, eRi, diA, diC);

            float4 cvn, cin;
            #pragma unroll
            for (int k = 0; k < 4; k++) {
                const float cv = lane_of(cvm1, k);   // field row ri-1 = ro
                const float ci = lane_of(cim1, k);
                const float mv = diff_v * cv * inv_kBT;
                const float mi = diff_i * ci * inv_kBT;
                set_lane(cvn, k, fminf(fmaxf(cv + DTV * (mv * lane_of(ldv, k)), 0.0f), 1.0f));
                set_lane(cin, k, fminf(fmaxf(ci + DTV * (mi * lane_of(ldi, k)), 0.0f), 1.0f));
            }
            const size_t o = basec + ((size_t)ro << 10);
            *(float4*)&out[o]       = cvn;
            *(float4*)&out[fld + o] = cin;
        }

        // ---- rotate ----
        dvA = dvB; dvB = dvC; diA = diB; diB = diC;
        hpdv = hdv; hpdi = hdi;
        cvm1 = cv0; cv0 = cvp1; cvp1 = cvp2;
        cim1 = ci0; ci0 = cip1; cip1 = cip2;
        etm1 = et0; et0 = etp1; etp1 = etp2;
        hcv_a = hcv_b; hcv_b = hcv_c;
        hci_a = hci_b; hci_b = hci_c;
        het_b = het_c;
        gcv_b = gcv_c; gci_b = gci_c;
    }
#undef LDROW
#undef LDE
}

extern "C" void kernel_launch(void* const* d_in, const int* in_sizes, int n_in,
                              void* d_out, int out_size)
{
    const float* cv  = (const float*)d_in[0];
    const float* ci  = (const float*)d_in[1];
    const float* eta = (const float*)d_in[2];
    const float* ev  = (const float*)d_in[3];
    const float* ei  = (const float*)d_in[4];
    const float* kbt = (const float*)d_in[5];
    const float* kv  = (const float*)d_in[6];
    const float* ki  = (const float*)d_in[7];
    const float* ke  = (const float*)d_in[8];
    const float* dv  = (const float*)d_in[9];
    const float* di  = (const float*)d_in[10];
    const float* L   = (const float*)d_in[11];
    float* out = (float*)d_out;

    dim3 block(128, 1, 1);
    dim3 grid(2, W / RPB, BAT);   // 2 blocks x 4 warps = 8 strips of 128 cols
    irr_warp_kernel<<<grid, block>>>(cv, ci, eta, ev, ei, kbt, kv, ki, ke,
                                     dv, di, L, out);
}

// round 14
// speedup vs baseline: 1.3177x; 1.0679x over previous
#include <cuda_runtime.h>
#include <cuda_bf16.h>

// IrradiationSingleTimestep — round 12: barrier-free warp-strip rolling stencil.
// vs round 10: (a) #pragma unroll 2 to kill rotation MOVs, (b) halo scalar
// loads deepened to ri+2 (full-iteration slack, same as vector rows),
// (c) row offset computed once per row.

#define W     1024
#define BAT   8
#define RPB   16
#define EPSV  1e-6f
#define DTV   1e-2f

__device__ __forceinline__ float4 lap4(float4 c, float L, float R, float4 u, float4 d) {
    float4 r;
    r.x = L   + c.y + u.x + d.x - 4.0f * c.x;
    r.y = c.x + c.z + u.y + d.y - 4.0f * c.y;
    r.z = c.y + c.w + u.z + d.z - 4.0f * c.z;
    r.w = c.z + R   + u.w + d.w - 4.0f * c.w;
    return r;
}
__device__ __forceinline__ float lane_of(const float4& v, int k) {
    return k == 0 ? v.x : (k == 1 ? v.y : (k == 2 ? v.z : v.w));
}
__device__ __forceinline__ void set_lane(float4& v, int k, float x) {
    if (k == 0) v.x = x; else if (k == 1) v.y = x; else if (k == 2) v.z = x; else v.w = x;
}

__global__ __launch_bounds__(128, 4)
void irr_warp_kernel(const float* __restrict__ cv_g,
                     const float* __restrict__ ci_g,
                     const float* __restrict__ eta_g,
                     const float* __restrict__ p_ev,
                     const float* __restrict__ p_ei,
                     const float* __restrict__ p_kbt,
                     const float* __restrict__ p_kv,
                     const float* __restrict__ p_ki,
                     const float* __restrict__ p_ke,
                     const float* __restrict__ p_dv,
                     const float* __restrict__ p_di,
                     const float* __restrict__ p_L,
                     float* __restrict__ out)
{
    const int lane  = threadIdx.x & 31;
    const int wl    = threadIdx.x >> 5;
    const int strip = blockIdx.x * 4 + wl;
    const int x     = (strip << 7) + (lane << 2);
    const int y0    = blockIdx.y * RPB;
    const int b     = blockIdx.z;

    const size_t plane = (size_t)W * W;
    const size_t fld   = (size_t)BAT * plane;
    const size_t baseb = (size_t)b * plane;
    const size_t basec = baseb + x;

    const float energy_v  = fabsf(*p_ev)  + 0.001f;
    const float energy_i  = fabsf(*p_ei)  + 0.001f;
    const float kBT       = fabsf(*p_kbt) + 0.001f;
    const float kappa_v   = fabsf(*p_kv)  + 0.001f;
    const float kappa_i   = fabsf(*p_ki)  + 0.001f;
    const float kappa_eta = fabsf(*p_ke)  + 0.001f;
    const float diff_v    = fabsf(*p_dv)  + 0.001f;
    const float diff_i    = fabsf(*p_di)  + 0.001f;
    const float Lp        = fabsf(*p_L)   + 0.001f;
    const float inv_kBT   = 1.0f / kBT;

#define ROFF(row) ((size_t)(((unsigned)(row) & (W - 1)) << 10))
#define LDV(p, off) (*(const float4*)((p) + basec + (off)))

    const bool edge = (lane == 0) | (lane == 31);
    const int  eo1  = (lane == 0) ? ((x - 1) & (W - 1)) : ((x + 4) & (W - 1));
    const int  eo2  = (lane == 0) ? ((x - 2) & (W - 1)) : ((x + 5) & (W - 1));
#define LDS1(p, col, off) ((p)[baseb + (off) + (col)])

    // ---- pipeline init ----
    const size_t offm1 = ROFF(y0 - 2), off0 = ROFF(y0 - 1), offp1 = ROFF(y0);

    float4 cvm1 = LDV(cv_g,  offm1), cv0 = LDV(cv_g,  off0), cvp1 = LDV(cv_g,  offp1);
    float4 cim1 = LDV(ci_g,  offm1), ci0 = LDV(ci_g,  off0), cip1 = LDV(ci_g,  offp1);
    float4 etm1 = LDV(eta_g, offm1), et0 = LDV(eta_g, off0), etp1 = LDV(eta_g, offp1);

    // Halo rolling: a = halo(ri-1), b = halo(ri), c = halo(ri+1); g at ri, ri+1
    float hcv_a = 0.f, hcv_b = 0.f, hcv_c = 0.f;
    float hci_a = 0.f, hci_b = 0.f, hci_c = 0.f;
    float het_b = 0.f, het_c = 0.f;
    float gcv_b = 0.f, gcv_c = 0.f, gci_b = 0.f, gci_c = 0.f;
    if (edge) {
        hcv_a = LDS1(cv_g,  eo1, offm1); hcv_b = LDS1(cv_g,  eo1, off0); hcv_c = LDS1(cv_g,  eo1, offp1);
        hci_a = LDS1(ci_g,  eo1, offm1); hci_b = LDS1(ci_g,  eo1, off0); hci_c = LDS1(ci_g,  eo1, offp1);
        het_b = LDS1(eta_g, eo1, off0);  het_c = LDS1(eta_g, eo1, offp1);
        gcv_b = LDS1(cv_g,  eo2, off0);  gcv_c = LDS1(cv_g,  eo2, offp1);
        gci_b = LDS1(ci_g,  eo2, off0);  gci_c = LDS1(ci_g,  eo2, offp1);
    }

    float4 dvA, dvB, diA, diB;
    float hpdv = 0.f, hpdi = 0.f;

    #pragma unroll 2
    for (int i = 0; i < RPB + 2; i++) {
        const int ri = y0 - 1 + i;

        // ---- issue loads of row ri+2 (consumed NEXT iteration) ----
        float4 cvp2, cip2, etp2;
        float hcv_d = 0.f, hci_d = 0.f, het_d = 0.f, gcv_d = 0.f, gci_d = 0.f;
        if (i <= RPB) {
            const size_t offp2 = ROFF(ri + 2);
            cvp2 = LDV(cv_g,  offp2);
            cip2 = LDV(ci_g,  offp2);
            etp2 = LDV(eta_g, offp2);
            if (edge) {
                hcv_d = LDS1(cv_g,  eo1, offp2);
                hci_d = LDS1(ci_g,  eo1, offp2);
                het_d = LDS1(eta_g, eo1, offp2);
                gcv_d = LDS1(cv_g,  eo2, offp2);
                gci_d = LDS1(ci_g,  eo2, offp2);
            }
        }

        // ---- field x-neighbors of row ri ----
        float cvL = __shfl_up_sync(0xffffffffu, cv0.w, 1);
        float ciL = __shfl_up_sync(0xffffffffu, ci0.w, 1);
        float etL = __shfl_up_sync(0xffffffffu, et0.w, 1);
        float cvR = __shfl_down_sync(0xffffffffu, cv0.x, 1);
        float ciR = __shfl_down_sync(0xffffffffu, ci0.x, 1);
        float etR = __shfl_down_sync(0xffffffffu, et0.x, 1);
        if (lane == 0)  { cvL = hcv_b; ciL = hci_b; etL = het_b; }
        if (lane == 31) { cvR = hcv_b; ciR = hci_b; etR = het_b; }

        // ---- dF row ri + eta_new ----
        const float4 lcv4 = lap4(cv0, cvL, cvR, cvm1, cvp1);
        const float4 lci4 = lap4(ci0, ciL, ciR, cim1, cip1);
        const float4 let4 = lap4(et0, etL, etR, etm1, etp1);

        float4 dvC, diC, en4;
        #pragma unroll
        for (int k = 0; k < 4; k++) {
            const float cv  = lane_of(cv0, k);
            const float ci  = lane_of(ci0, k);
            const float eta = lane_of(et0, k);

            const float cs  = 1.0f - cv - ci;
            const float lcv = __logf(fmaxf(cv, EPSV));
            const float lci = __logf(fmaxf(ci, EPSV));
            const float lcs = __logf(fmaxf(cs, EPSV));

            const float em1 = eta - 1.0f;
            const float h   = em1 * em1;
            const float jj  = eta * eta;

            const float dfs_dcv = energy_v + kBT * (lcv - lcs);
            const float dfs_dci = energy_i + kBT * (lci - lcs);

            set_lane(dvC, k, h * dfs_dcv + jj * (2.0f * (cv - 1.0f)) - kappa_v * lane_of(lcv4, k));
            set_lane(diC, k, h * dfs_dci + jj * (2.0f * ci)          - kappa_i * lane_of(lci4, k));

            const float fs = energy_v * cv + energy_i * ci
                           + kBT * (cv * lcv + ci * lci + cs * lcs);
            const float cq = cv - 1.0f;
            const float fv = cq * cq + ci * ci;
            const float dFe = fs * (2.0f * em1) + fv * (2.0f * eta)
                            - kappa_eta * lane_of(let4, k);
            set_lane(en4, k, fminf(fmaxf(eta - DTV * (Lp * dFe), 0.0f), 1.0f));
        }

        if (i >= 1 && i <= RPB) {
            *(float4*)&out[2 * fld + basec + ROFF(ri)] = en4;
        }

        // ---- halo dF at (eo1, ri): edge lanes, all inputs prefetched ----
        float hdv = 0.f, hdi = 0.f;
        if (edge) {
            const float inner_cv = (lane == 0) ? cv0.x : cv0.w;
            const float inner_ci = (lane == 0) ? ci0.x : ci0.w;
            const float lap_hcv = gcv_b + inner_cv + hcv_a + hcv_c - 4.0f * hcv_b;
            const float lap_hci = gci_b + inner_ci + hci_a + hci_c - 4.0f * hci_b;

            const float cs  = 1.0f - hcv_b - hci_b;
            const float lcv = __logf(fmaxf(hcv_b, EPSV));
            const float lci = __logf(fmaxf(hci_b, EPSV));
            const float lcs = __logf(fmaxf(cs, EPSV));
            const float em1 = het_b - 1.0f;
            const float h   = em1 * em1;
            const float jj  = het_b * het_b;

            hdv = h * (energy_v + kBT * (lcv - lcs)) + jj * (2.0f * (hcv_b - 1.0f)) - kappa_v * lap_hcv;
            hdi = h * (energy_i + kBT * (lci - lcs)) + jj * (2.0f * hci_b)          - kappa_i * lap_hci;
        }

        // ---- output row ro = ri-1 ----
        if (i >= 2) {
            float eLv = __shfl_up_sync(0xffffffffu, dvB.w, 1);
            float eLi = __shfl_up_sync(0xffffffffu, diB.w, 1);
            float eRv = __shfl_down_sync(0xffffffffu, dvB.x, 1);
            float eRi = __shfl_down_sync(0xffffffffu, diB.x, 1);
            if (lane == 0)  { eLv = hpdv; eLi = hpdi; }
            if (lane == 31) { eRv = hpdv; eRi = hpdi; }

            const float4 ldv = lap4(dvB, eLv, eRv, dvA, dvC);
            const float4 ldi = lap4(diB, eLi, eRi, diA, diC);

            float4 cvn, cin;
            #pragma unroll
            for (int k = 0; k < 4; k++) {
                const float cv = lane_of(cvm1, k);   // field row ri-1
                const float ci = lane_of(cim1, k);
                const float mv = diff_v * cv * inv_kBT;
                const float mi = diff_i * ci * inv_kBT;
                set_lane(cvn, k, fminf(fmaxf(cv + DTV * (mv * lane_of(ldv, k)), 0.0f), 1.0f));
                set_lane(cin, k, fminf(fmaxf(ci + DTV * (mi * lane_of(ldi, k)), 0.0f), 1.0f));
            }
            const size_t o = basec + ROFF(ri - 1);
            *(float4*)&out[o]       = cvn;
            *(float4*)&out[fld + o] = cin;
        }

        // ---- rotate (renamed away by unroll) ----
        dvA = dvB; dvB = dvC; diA = diB; diB = diC;
        hpdv = hdv; hpdi = hdi;
        cvm1 = cv0; cv0 = cvp1; cvp1 = cvp2;
        cim1 = ci0; ci0 = cip1; cip1 = cip2;
        etm1 = et0; et0 = etp1; etp1 = etp2;
        hcv_a = hcv_b; hcv_b = hcv_c; hcv_c = hcv_d;
        hci_a = hci_b; hci_b = hci_c; hci_c = hci_d;
        het_b = het_c; het_c = het_d;
        gcv_b = gcv_c; gcv_c = gcv_d;
        gci_b = gci_c; gci_c = gci_d;
    }
#undef ROFF
#undef LDV
#undef LDS1
}

extern "C" void kernel_launch(void* const* d_in, const int* in_sizes, int n_in,
                              void* d_out, int out_size)
{
    const float* cv  = (const float*)d_in[0];
    const float* ci  = (const float*)d_in[1];
    const float* eta = (const float*)d_in[2];
    const float* ev  = (const float*)d_in[3];
    const float* ei  = (const float*)d_in[4];
    const float* kbt = (const float*)d_in[5];
    const float* kv  = (const float*)d_in[6];
    const float* ki  = (const float*)d_in[7];
    const float* ke  = (const float*)d_in[8];
    const float* dv  = (const float*)d_in[9];
    const float* di  = (const float*)d_in[10];
    const float* L   = (const float*)d_in[11];
    float* out = (float*)d_out;

    dim3 block(128, 1, 1);
    dim3 grid(2, W / RPB, BAT);
    irr_warp_kernel<<<grid, block>>>(cv, ci, eta, ev, ei, kbt, kv, ki, ke,
                                     dv, di, L, out);
}